// round 5
// baseline (speedup 1.0000x reference)
#include <cuda_runtime.h>
#include <cuda_bf16.h>
#include <math.h>
#include <stdint.h>

#define BB 16
#define CC 256
#define LL 2048
#define EE 512
#define NN 64
#define HH 512
#define H2 1024

// weight offsets in bf16 scratch
#define W1_OFF 0                      // in_W   512x256
#define W2_OFF 131072                 // s1_oW 1024x512
#define W3_OFF 655360                 // s2_oW 1024x512
#define W4_OFF 1179648                // out_W  512x256
#define WTOT   1310720

// ---------------- scratch ----------------
__device__ float          g_e[BB * HH];
__device__ float2         g_z [2 * HH * NN];
__device__ float2         g_ct[2 * HH * NN];
__device__ float          g_u[BB * HH * LL];
__device__ float          g_t[(size_t)BB * H2 * LL];
__device__ __nv_bfloat16  g_bh[BB * HH * LL];
__device__ __nv_bfloat16  g_bl[BB * HH * LL];
__device__ __nv_bfloat16  g_wh[WTOT];
__device__ __nv_bfloat16  g_wl[WTOT];

// ---------------- math helpers ----------------
__device__ __forceinline__ float sigf(float x) {
    return __fdividef(1.f, 1.f + __expf(-x));
}
__device__ __forceinline__ float tanh_fast(float x) {
    return fmaf(2.f, __fdividef(1.f, 1.f + __expf(-2.f * x)), -1.f);
}
__device__ __forceinline__ float geluf(float x) {
    float t = x * fmaf(0.044715f, x * x, 1.f);
    return x * sigf(1.5957691216057308f * t);
}
__device__ __forceinline__ uint32_t pack_bf16(__nv_bfloat16 a, __nv_bfloat16 b) {
    __nv_bfloat162 v(a, b);
    return *(uint32_t*)&v;
}
__device__ __forceinline__ void split2(float v0, float v1, uint32_t& hi, uint32_t& lo) {
    __nv_bfloat16 h0 = __float2bfloat16(v0);
    __nv_bfloat16 h1 = __float2bfloat16(v1);
    __nv_bfloat16 q0 = __float2bfloat16(v0 - __bfloat162float(h0));
    __nv_bfloat16 q1 = __float2bfloat16(v1 - __bfloat162float(h1));
    hi = pack_bf16(h0, h1);
    lo = pack_bf16(q0, q1);
}

// ---------------- fused diffusion proj + input bias: e[b,o] ----------------
__global__ void k_debias(const float* __restrict__ demb, const float* __restrict__ dpW,
                         const float* __restrict__ dpb, const float* __restrict__ inW,
                         const float* __restrict__ inb, float* __restrict__ e) {
    int b = blockIdx.x;
    int t = threadIdx.x;  // 256
    __shared__ float se[EE];
    __shared__ float sd[CC];
    for (int i = t; i < EE; i += 256) se[i] = demb[b * EE + i];
    __syncthreads();
    {
        float acc = 0.f;
#pragma unroll 8
        for (int k = 0; k < EE; k++) acc = fmaf(dpW[(size_t)t * EE + k], se[k], acc);
        sd[t] = acc + dpb[t];
    }
    __syncthreads();
    for (int o = t; o < HH; o += 256) {
        float acc = 0.f;
#pragma unroll 8
        for (int k = 0; k < CC; k++) acc = fmaf(inW[(size_t)o * CC + k], sd[k], acc);
        e[b * HH + o] = acc + inb[o];
    }
}

// ---------------- weight split fp32 -> bf16 hi/lo ----------------
__global__ void k_wsplit(const float* __restrict__ w, __nv_bfloat16* __restrict__ wh,
                         __nv_bfloat16* __restrict__ wl, int n) {
    int i = blockIdx.x * 256 + threadIdx.x;
    if (i >= n) return;
    float v = w[i];
    __nv_bfloat16 h = __float2bfloat16(v);
    wh[i] = h;
    wl[i] = __float2bfloat16(v - __bfloat162float(h));
}

// ---------------- x split (vectorized) ----------------
__global__ void k_x2bf(const float* __restrict__ x, __nv_bfloat16* __restrict__ xh,
                       __nv_bfloat16* __restrict__ xl) {
    int i4 = blockIdx.x * 256 + threadIdx.x;  // over total/4
    float4 v = *(const float4*)(x + (size_t)i4 * 4);
    uint2 h, l;
    split2(v.x, v.y, h.x, l.x);
    split2(v.z, v.w, h.y, l.y);
    *(uint2*)(xh + (size_t)i4 * 4) = h;
    *(uint2*)(xl + (size_t)i4 * 4) = l;
}

// ---------------- SSM precompute ----------------
__global__ void k_prec(const float* __restrict__ log_dt, const float* __restrict__ Are,
                       const float* __restrict__ Aim, const float* __restrict__ Cre,
                       const float* __restrict__ Cim, float2* __restrict__ z,
                       float2* __restrict__ ct) {
    int i = blockIdx.x * blockDim.x + threadIdx.x;
    if (i >= HH * NN) return;
    int h = i / NN;
    float dt = expf(log_dt[h]);
    float A_r = Are[i], A_i = Aim[i];
    float ar = A_r * dt, ai = A_i * dt;
    float er = expf(ar);
    float s, c0;
    sincosf(ai, &s, &c0);
    float zr = er * c0, zi = er * s;
    float wr = zr - 1.f, wi = zi;
    float den = A_r * A_r + A_i * A_i;
    float inv = 1.f / den;
    float qr = (wr * A_r + wi * A_i) * inv;
    float qi = (wi * A_r - wr * A_i) * inv;
    float cr = Cre[i], ci = Cim[i];
    ct[i] = make_float2(2.f * (cr * qr - ci * qi), 2.f * (cr * qi + ci * qr));
    z[i] = make_float2(zr, zi);
}

// ---------------- diagonal SSM recurrence + D-skip + GELU -> bf16 hi/lo ----------------
__global__ void k_ssm(const float* __restrict__ in, __nv_bfloat16* __restrict__ outh,
                      __nv_bfloat16* __restrict__ outl,
                      const float2* __restrict__ zarr, const float2* __restrict__ ctarr,
                      const float* __restrict__ Dv) {
    int w = (blockIdx.x * blockDim.x + threadIdx.x) >> 5;
    int lane = threadIdx.x & 31;
    int b = w >> 9, h = w & (HH - 1);
    float2 z0 = zarr[h * NN + lane];
    float2 z1 = zarr[h * NN + 32 + lane];
    float2 c0 = ctarr[h * NN + lane];
    float2 c1 = ctarr[h * NN + 32 + lane];
    float Dh = Dv[h];
    const float4* ip = (const float4*)(in + (size_t)(b * HH + h) * LL);
    __nv_bfloat16* oph = outh + (size_t)(b * HH + h) * LL;
    __nv_bfloat16* opl = outl + (size_t)(b * HH + h) * LL;
    float s0r = 0.f, s0i = 0.f, s1r = 0.f, s1i = 0.f;
    float4 u4 = __ldg(ip);
    for (int l4 = 0; l4 < LL / 4; l4++) {
        float4 nx;
        if (l4 + 1 < LL / 4) nx = __ldg(ip + l4 + 1);
        float o[4];
#pragma unroll
        for (int j = 0; j < 4; j++) {
            float u = (j == 0) ? u4.x : (j == 1) ? u4.y : (j == 2) ? u4.z : u4.w;
            float sr = s0r, si = s0i;
            s0r = fmaf(z0.x, sr, fmaf(-z0.y, si, u));
            s0i = fmaf(z0.x, si, z0.y * sr);
            sr = s1r; si = s1i;
            s1r = fmaf(z1.x, sr, fmaf(-z1.y, si, u));
            s1i = fmaf(z1.x, si, z1.y * sr);
            float p = c0.x * s0r;
            p = fmaf(-c0.y, s0i, p);
            p = fmaf(c1.x, s1r, p);
            p = fmaf(-c1.y, s1i, p);
#pragma unroll
            for (int off = 16; off; off >>= 1) p += __shfl_xor_sync(0xffffffffu, p, off);
            o[j] = fmaf(Dh, u, p);
        }
        if (lane == 0) {
            float g0 = geluf(o[0]), g1 = geluf(o[1]);
            float g2 = geluf(o[2]), g3 = geluf(o[3]);
            uint2 hv, lv;
            split2(g0, g1, hv.x, lv.x);
            split2(g2, g3, hv.y, lv.y);
            *(uint2*)(oph + l4 * 4) = hv;
            *(uint2*)(opl + l4 * 4) = lv;
        }
        u4 = nx;
    }
}

// ======================================================================
// pure-bf16 split-precision tensor-core GEMM (operands pre-split)
// D = Ah*Bh + Ah*Bl + Al*Bh ; block 128x128, K-chunk 16, 8 warps (2x4)
// ======================================================================
#define SA_STR 24
#define SB_STR 136

__device__ __forceinline__ void cp16(uint32_t dst, const void* src) {
    asm volatile("cp.async.ca.shared.global [%0], [%1], 16;\n" :: "r"(dst), "l"(src));
}
__device__ __forceinline__ void ldsm_x4(uint32_t& r0, uint32_t& r1, uint32_t& r2,
                                        uint32_t& r3, uint32_t addr) {
    asm volatile("ldmatrix.sync.aligned.m8n8.x4.shared.b16 {%0,%1,%2,%3}, [%4];"
                 : "=r"(r0), "=r"(r1), "=r"(r2), "=r"(r3) : "r"(addr));
}
__device__ __forceinline__ void ldsm_x2t(uint32_t& r0, uint32_t& r1, uint32_t addr) {
    asm volatile("ldmatrix.sync.aligned.m8n8.x2.trans.shared.b16 {%0,%1}, [%2];"
                 : "=r"(r0), "=r"(r1) : "r"(addr));
}
__device__ __forceinline__ void mma16816(float* c, const uint32_t* a, const uint32_t* b) {
    asm volatile("mma.sync.aligned.m16n8k16.row.col.f32.bf16.bf16.f32 "
                 "{%0,%1,%2,%3}, {%4,%5,%6,%7}, {%8,%9}, {%0,%1,%2,%3};"
                 : "+f"(c[0]), "+f"(c[1]), "+f"(c[2]), "+f"(c[3])
                 : "r"(a[0]), "r"(a[1]), "r"(a[2]), "r"(a[3]), "r"(b[0]), "r"(b[1]));
}

__global__ __launch_bounds__(256, 2)
void k_gemm_bf(const __nv_bfloat16* __restrict__ Ah_, const __nv_bfloat16* __restrict__ Al_,
               const __nv_bfloat16* __restrict__ Bh_, const __nv_bfloat16* __restrict__ Bl_,
               const float* __restrict__ bias, int bias_per_batch,
               float* __restrict__ Y, int O, int K,
               const float* __restrict__ xres, int final_mode) {
    __shared__ __align__(16) __nv_bfloat16 sAh[2][128][SA_STR];
    __shared__ __align__(16) __nv_bfloat16 sAl[2][128][SA_STR];
    __shared__ __align__(16) __nv_bfloat16 sBh[2][16][SB_STR];
    __shared__ __align__(16) __nv_bfloat16 sBl[2][16][SB_STR];

    int t = threadIdx.x, lane = t & 31, warp = t >> 5;
    int wo = warp >> 2, wl = warp & 3;
    int o0 = blockIdx.y * 128, l0 = blockIdx.x * 128, b = blockIdx.z;
    const __nv_bfloat16* BhB = Bh_ + (size_t)b * K * LL;
    const __nv_bfloat16* BlB = Bl_ + (size_t)b * K * LL;
    int nk = K / 16;

    int arow = t >> 1, acol = (t & 1) * 8;
    int brow = t >> 4, bcol = (t & 15) * 8;

    float acc[4][4][4];
#pragma unroll
    for (int i = 0; i < 4; i++)
#pragma unroll
        for (int j = 0; j < 4; j++)
#pragma unroll
            for (int q = 0; q < 4; q++) acc[i][j][q] = 0.f;

#define STAGE(buf, kb)                                                                     \
    do {                                                                                   \
        cp16((uint32_t)__cvta_generic_to_shared(&sAh[buf][arow][acol]),                    \
             Ah_ + (size_t)(o0 + arow) * K + (kb) + acol);                                 \
        cp16((uint32_t)__cvta_generic_to_shared(&sAl[buf][arow][acol]),                    \
             Al_ + (size_t)(o0 + arow) * K + (kb) + acol);                                 \
        cp16((uint32_t)__cvta_generic_to_shared(&sBh[buf][brow][bcol]),                    \
             BhB + (size_t)((kb) + brow) * LL + l0 + bcol);                                \
        cp16((uint32_t)__cvta_generic_to_shared(&sBl[buf][brow][bcol]),                    \
             BlB + (size_t)((kb) + brow) * LL + l0 + bcol);                                \
        asm volatile("cp.async.commit_group;\n");                                         \
    } while (0)

    STAGE(0, 0);
    asm volatile("cp.async.wait_group 0;\n");
    __syncthreads();

    int aRow = wo * 64 + (lane & 15);
    int aCol = (lane >> 4) * 8;
    uint32_t aOff = (uint32_t)((aRow * SA_STR + aCol) * 2);
    uint32_t bOff = (uint32_t)(((lane & 15) * SB_STR + wl * 32) * 2);

    for (int kc = 0; kc < nk; kc++) {
        int cur = kc & 1, nxt = cur ^ 1;
        bool more = (kc + 1) < nk;
        if (more) STAGE(nxt, (kc + 1) * 16);

        uint32_t aHb = (uint32_t)__cvta_generic_to_shared(&sAh[cur][0][0]);
        uint32_t aLb = (uint32_t)__cvta_generic_to_shared(&sAl[cur][0][0]);
        uint32_t bHb = (uint32_t)__cvta_generic_to_shared(&sBh[cur][0][0]);
        uint32_t bLb = (uint32_t)__cvta_generic_to_shared(&sBl[cur][0][0]);

        uint32_t aH[4][4], aL[4][4], bH[4][2], bL[4][2];
#pragma unroll
        for (int mi = 0; mi < 4; mi++) {
            uint32_t off = aOff + (uint32_t)(mi * 16 * SA_STR * 2);
            ldsm_x4(aH[mi][0], aH[mi][1], aH[mi][2], aH[mi][3], aHb + off);
            ldsm_x4(aL[mi][0], aL[mi][1], aL[mi][2], aL[mi][3], aLb + off);
        }
#pragma unroll
        for (int ni = 0; ni < 4; ni++) {
            uint32_t off = bOff + (uint32_t)(ni * 8 * 2);
            ldsm_x2t(bH[ni][0], bH[ni][1], bHb + off);
            ldsm_x2t(bL[ni][0], bL[ni][1], bLb + off);
        }
#pragma unroll
        for (int mi = 0; mi < 4; mi++)
#pragma unroll
            for (int ni = 0; ni < 4; ni++) {
                mma16816(acc[mi][ni], aH[mi], bH[ni]);
                mma16816(acc[mi][ni], aH[mi], bL[ni]);
                mma16816(acc[mi][ni], aL[mi], bH[ni]);
            }
        if (more) asm volatile("cp.async.wait_group 0;\n");
        __syncthreads();
    }

    // ---- epilogue ----
    int g = lane >> 2, t4 = lane & 3;
#pragma unroll
    for (int mi = 0; mi < 4; mi++) {
#pragma unroll
        for (int ni = 0; ni < 4; ni++) {
            int row0 = o0 + wo * 64 + mi * 16 + g;
            int row1 = row0 + 8;
            int col = l0 + wl * 32 + ni * 8 + t4 * 2;
            float b0 = bias_per_batch ? bias[b * O + row0] : bias[row0];
            float b1 = bias_per_batch ? bias[b * O + row1] : bias[row1];
            float v00 = acc[mi][ni][0] + b0, v01 = acc[mi][ni][1] + b0;
            float v10 = acc[mi][ni][2] + b1, v11 = acc[mi][ni][3] + b1;
            if (!final_mode) {
                float* y0 = Y + (size_t)b * O * LL + (size_t)row0 * LL + col;
                float* y1 = Y + (size_t)b * O * LL + (size_t)row1 * LL + col;
                *(float2*)y0 = make_float2(v00, v01);
                *(float2*)y1 = make_float2(v10, v11);
            } else {
                const float s = 0.70710678118654752f;
                {
                    int o = row0;
                    if (o < CC) {
                        size_t idx = (size_t)(b * CC + o) * LL + col;
                        float2 xv = *(const float2*)(xres + idx);
                        *(float2*)(Y + idx) = make_float2((xv.x + v00) * s, (xv.y + v01) * s);
                    } else {
                        size_t idx = (size_t)BB * CC * LL + (size_t)(b * CC + (o - CC)) * LL + col;
                        *(float2*)(Y + idx) = make_float2(v00, v01);
                    }
                }
                {
                    int o = row1;
                    if (o < CC) {
                        size_t idx = (size_t)(b * CC + o) * LL + col;
                        float2 xv = *(const float2*)(xres + idx);
                        *(float2*)(Y + idx) = make_float2((xv.x + v10) * s, (xv.y + v11) * s);
                    } else {
                        size_t idx = (size_t)BB * CC * LL + (size_t)(b * CC + (o - CC)) * LL + col;
                        *(float2*)(Y + idx) = make_float2(v10, v11);
                    }
                }
            }
        }
    }
#undef STAGE
}

// ---------------- GLU (fp32 -> fp32) ----------------
__global__ void k_glu(const float* __restrict__ t, float* __restrict__ u) {
    int i = blockIdx.x * 256 + threadIdx.x;
    int b = i / (HH * LL);
    int r = i - b * HH * LL;
    const float* tb = t + (size_t)b * H2 * LL;
    float a = tb[r];
    float g = tb[r + HH * LL];
    u[i] = a * sigf(g);
}

// ---------------- LayerNorm over channels (in-place fp32) ----------------
__global__ void k_ln(float* __restrict__ u, const float* __restrict__ g,
                     const float* __restrict__ be) {
    int i = blockIdx.x * blockDim.x + threadIdx.x;
    int b = i / LL, l = i - b * LL;
    float* base = u + (size_t)b * HH * LL + l;
    float sum = 0.f, ss = 0.f;
#pragma unroll 8
    for (int h = 0; h < HH; h++) {
        float v = base[(size_t)h * LL];
        sum += v;
        ss = fmaf(v, v, ss);
    }
    float mu = sum * (1.f / HH);
    float var = ss * (1.f / HH) - mu * mu;
    float rs = rsqrtf(var + 1e-5f);
#pragma unroll 8
    for (int h = 0; h < HH; h++) {
        float v = base[(size_t)h * LL];
        base[(size_t)h * LL] = (v - mu) * rs * __ldg(g + h) + __ldg(be + h);
    }
}

// ---------------- gate/filter activation -> bf16 hi/lo ----------------
__global__ void k_act(const float* __restrict__ u, __nv_bfloat16* __restrict__ zh,
                      __nv_bfloat16* __restrict__ zl) {
    int i4 = blockIdx.x * 256 + threadIdx.x;  // over B*C*L/4
    int b = i4 / (CC * LL / 4);
    int r = i4 - b * (CC * LL / 4);
    const float* ub = u + (size_t)b * HH * LL;
    float4 gt = *(const float4*)(ub + (size_t)r * 4);
    float4 fl = *(const float4*)(ub + (size_t)CC * LL + (size_t)r * 4);
    float v0 = sigf(gt.x) * tanh_fast(fl.x);
    float v1 = sigf(gt.y) * tanh_fast(fl.y);
    float v2 = sigf(gt.z) * tanh_fast(fl.z);
    float v3 = sigf(gt.w) * tanh_fast(fl.w);
    uint2 h, l;
    split2(v0, v1, h.x, l.x);
    split2(v2, v3, h.y, l.y);
    *(uint2*)(zh + (size_t)i4 * 4) = h;
    *(uint2*)(zl + (size_t)i4 * 4) = l;
}

// ---------------- launch ----------------
extern "C" void kernel_launch(void* const* d_in, const int* in_sizes, int n_in,
                              void* d_out, int out_size) {
    const float* x    = (const float*)d_in[0];
    const float* demb = (const float*)d_in[1];
    const float* dpW  = (const float*)d_in[2];
    const float* dpb  = (const float*)d_in[3];
    const float* inW  = (const float*)d_in[4];
    const float* inb  = (const float*)d_in[5];
    const float* outW = (const float*)d_in[6];
    const float* outb = (const float*)d_in[7];
    const float* ln1g = (const float*)d_in[8];
    const float* ln1b = (const float*)d_in[9];
    const float* ln2g = (const float*)d_in[10];
    const float* ln2b = (const float*)d_in[11];
    const float* s1_logdt = (const float*)d_in[12];
    const float* s1_Are   = (const float*)d_in[13];
    const float* s1_Aim   = (const float*)d_in[14];
    const float* s1_Cre   = (const float*)d_in[15];
    const float* s1_Cim   = (const float*)d_in[16];
    const float* s1_D     = (const float*)d_in[17];
    const float* s1_oW    = (const float*)d_in[18];
    const float* s1_ob    = (const float*)d_in[19];
    const float* s2_logdt = (const float*)d_in[20];
    const float* s2_Are   = (const float*)d_in[21];
    const float* s2_Aim   = (const float*)d_in[22];
    const float* s2_Cre   = (const float*)d_in[23];
    const float* s2_Cim   = (const float*)d_in[24];
    const float* s2_D     = (const float*)d_in[25];
    const float* s2_oW    = (const float*)d_in[26];
    const float* s2_ob    = (const float*)d_in[27];

    float* out = (float*)d_out;

    float *du, *dt, *de;
    float2 *dz, *dct;
    __nv_bfloat16 *bh, *bl, *wh, *wlp;
    cudaGetSymbolAddress((void**)&du, g_u);
    cudaGetSymbolAddress((void**)&dt, g_t);
    cudaGetSymbolAddress((void**)&de, g_e);
    cudaGetSymbolAddress((void**)&dz, g_z);
    cudaGetSymbolAddress((void**)&dct, g_ct);
    cudaGetSymbolAddress((void**)&bh, g_bh);
    cudaGetSymbolAddress((void**)&bl, g_bl);
    cudaGetSymbolAddress((void**)&wh, g_wh);
    cudaGetSymbolAddress((void**)&wlp, g_wl);

    const int HN = HH * NN;

    // 1-3: prerequisites of in-proj GEMM
    k_debias<<<BB, 256>>>(demb, dpW, dpb, inW, inb, de);
    k_wsplit<<<(HH * CC + 255) / 256, 256>>>(inW, wh + W1_OFF, wlp + W1_OFF, HH * CC);
    k_x2bf<<<BB * CC * LL / 4 / 256, 256>>>(x, bh, bl);
    // 4: PROFILED — in-proj GEMM: u = in_W @ x + e(b,:)
    k_gemm_bf<<<dim3(LL / 128, HH / 128, BB), 256>>>(wh + W1_OFF, wlp + W1_OFF, bh, bl,
                                                     de, 1, du, HH, CC, nullptr, 0);
    k_prec<<<(HN + 255) / 256, 256>>>(s1_logdt, s1_Are, s1_Aim, s1_Cre, s1_Cim, dz, dct);
    k_wsplit<<<(H2 * HH + 255) / 256, 256>>>(s1_oW, wh + W2_OFF, wlp + W2_OFF, H2 * HH);
    // S4 layer 1
    k_ssm<<<(BB * HH) / 4, 128>>>(du, bh, bl, dz, dct, s1_D);
    k_gemm_bf<<<dim3(LL / 128, H2 / 128, BB), 256>>>(wh + W2_OFF, wlp + W2_OFF, bh, bl,
                                                     s1_ob, 0, dt, H2, HH, nullptr, 0);
    k_glu<<<BB * HH * LL / 256, 256>>>(dt, du);
    k_ln<<<BB * LL / 256, 256>>>(du, ln1g, ln1b);
    // S4 layer 2
    k_prec<<<(HN + 255) / 256, 256>>>(s2_logdt, s2_Are, s2_Aim, s2_Cre, s2_Cim, dz + HN, dct + HN);
    k_wsplit<<<(H2 * HH + 255) / 256, 256>>>(s2_oW, wh + W3_OFF, wlp + W3_OFF, H2 * HH);
    k_ssm<<<(BB * HH) / 4, 128>>>(du, bh, bl, dz + HN, dct + HN, s2_D);
    k_gemm_bf<<<dim3(LL / 128, H2 / 128, BB), 256>>>(wh + W3_OFF, wlp + W3_OFF, bh, bl,
                                                     s2_ob, 0, dt, H2, HH, nullptr, 0);
    k_glu<<<BB * HH * LL / 256, 256>>>(dt, du);
    k_ln<<<BB * LL / 256, 256>>>(du, ln2g, ln2b);
    // gate/filter -> bf16 pair
    k_act<<<BB * CC * LL / 4 / 256, 256>>>(du, bh, bl);
    k_wsplit<<<(HH * CC + 255) / 256, 256>>>(outW, wh + W4_OFF, wlp + W4_OFF, HH * CC);
    // out-proj fused with residual/skip split
    k_gemm_bf<<<dim3(LL / 128, HH / 128, BB), 256>>>(wh + W4_OFF, wlp + W4_OFF, bh, bl,
                                                     outb, 0, out, HH, CC, x, 1);
}

// round 6
// speedup vs baseline: 1.2309x; 1.2309x over previous
#include <cuda_runtime.h>
#include <cuda_bf16.h>
#include <math.h>
#include <stdint.h>

#define BB 16
#define CC 256
#define LL 2048
#define EE 512
#define NN 64
#define HH 512
#define H2 1024

// weight offsets in bf16 scratch
#define W1_OFF 0                      // in_W   512x256
#define W2_OFF 131072                 // s1_oW 1024x512
#define W3_OFF 655360                 // s2_oW 1024x512
#define W4_OFF 1179648                // out_W  512x256
#define WTOT   1310720

// ---------------- scratch ----------------
__device__ float          g_e[BB * HH];
__device__ float2         g_z [2 * HH * NN];
__device__ float2         g_ct[2 * HH * NN];
__device__ float          g_u[BB * HH * LL];
__device__ float          g_t[(size_t)BB * H2 * LL];
__device__ __nv_bfloat16  g_bh[BB * HH * LL];
__device__ __nv_bfloat16  g_bl[BB * HH * LL];
__device__ __nv_bfloat16  g_wh[WTOT];
__device__ __nv_bfloat16  g_wl[WTOT];

// ---------------- math helpers ----------------
__device__ __forceinline__ float sigf(float x) {
    return __fdividef(1.f, 1.f + __expf(-x));
}
__device__ __forceinline__ float tanh_fast(float x) {
    return fmaf(2.f, __fdividef(1.f, 1.f + __expf(-2.f * x)), -1.f);
}
__device__ __forceinline__ float geluf(float x) {
    float t = x * fmaf(0.044715f, x * x, 1.f);
    return x * sigf(1.5957691216057308f * t);
}
__device__ __forceinline__ uint32_t pack_bf16(__nv_bfloat16 a, __nv_bfloat16 b) {
    __nv_bfloat162 v(a, b);
    return *(uint32_t*)&v;
}
__device__ __forceinline__ void split2(float v0, float v1, uint32_t& hi, uint32_t& lo) {
    __nv_bfloat16 h0 = __float2bfloat16(v0);
    __nv_bfloat16 h1 = __float2bfloat16(v1);
    __nv_bfloat16 q0 = __float2bfloat16(v0 - __bfloat162float(h0));
    __nv_bfloat16 q1 = __float2bfloat16(v1 - __bfloat162float(h1));
    hi = pack_bf16(h0, h1);
    lo = pack_bf16(q0, q1);
}

// ---------------- packed f32x2 (Blackwell 2x-rate fp32) ----------------
__device__ __forceinline__ uint64_t packf2(float lo, float hi) {
    uint64_t r;
    asm("mov.b64 %0, {%1,%2};" : "=l"(r) : "f"(lo), "f"(hi));
    return r;
}
__device__ __forceinline__ void unpackf2(uint64_t v, float& lo, float& hi) {
    asm("mov.b64 {%0,%1}, %2;" : "=f"(lo), "=f"(hi) : "l"(v));
}
__device__ __forceinline__ uint64_t fma2(uint64_t a, uint64_t b, uint64_t c) {
    uint64_t d;
    asm("fma.rn.f32x2 %0, %1, %2, %3;" : "=l"(d) : "l"(a), "l"(b), "l"(c));
    return d;
}
__device__ __forceinline__ uint64_t mul2(uint64_t a, uint64_t b) {
    uint64_t d;
    asm("mul.rn.f32x2 %0, %1, %2;" : "=l"(d) : "l"(a), "l"(b));
    return d;
}

// ---------------- fused diffusion proj + input bias: e[b,o] ----------------
__global__ void k_debias(const float* __restrict__ demb, const float* __restrict__ dpW,
                         const float* __restrict__ dpb, const float* __restrict__ inW,
                         const float* __restrict__ inb, float* __restrict__ e) {
    int b = blockIdx.x;
    int t = threadIdx.x;  // 256
    __shared__ float se[EE];
    __shared__ float sd[CC];
    for (int i = t; i < EE; i += 256) se[i] = demb[b * EE + i];
    __syncthreads();
    {
        float acc = 0.f;
#pragma unroll 8
        for (int k = 0; k < EE; k++) acc = fmaf(dpW[(size_t)t * EE + k], se[k], acc);
        sd[t] = acc + dpb[t];
    }
    __syncthreads();
    for (int o = t; o < HH; o += 256) {
        float acc = 0.f;
#pragma unroll 8
        for (int k = 0; k < CC; k++) acc = fmaf(inW[(size_t)o * CC + k], sd[k], acc);
        e[b * HH + o] = acc + inb[o];
    }
}

// ---------------- weight split fp32 -> bf16 hi/lo ----------------
__global__ void k_wsplit(const float* __restrict__ w, __nv_bfloat16* __restrict__ wh,
                         __nv_bfloat16* __restrict__ wl, int n) {
    int i = blockIdx.x * 256 + threadIdx.x;
    if (i >= n) return;
    float v = w[i];
    __nv_bfloat16 h = __float2bfloat16(v);
    wh[i] = h;
    wl[i] = __float2bfloat16(v - __bfloat162float(h));
}

// ---------------- x split (vectorized) ----------------
__global__ void k_x2bf(const float* __restrict__ x, __nv_bfloat16* __restrict__ xh,
                       __nv_bfloat16* __restrict__ xl) {
    int i4 = blockIdx.x * 256 + threadIdx.x;  // over total/4
    float4 v = *(const float4*)(x + (size_t)i4 * 4);
    uint2 h, l;
    split2(v.x, v.y, h.x, l.x);
    split2(v.z, v.w, h.y, l.y);
    *(uint2*)(xh + (size_t)i4 * 4) = h;
    *(uint2*)(xl + (size_t)i4 * 4) = l;
}

// ---------------- SSM precompute ----------------
__global__ void k_prec(const float* __restrict__ log_dt, const float* __restrict__ Are,
                       const float* __restrict__ Aim, const float* __restrict__ Cre,
                       const float* __restrict__ Cim, float2* __restrict__ z,
                       float2* __restrict__ ct) {
    int i = blockIdx.x * blockDim.x + threadIdx.x;
    if (i >= HH * NN) return;
    int h = i / NN;
    float dt = expf(log_dt[h]);
    float A_r = Are[i], A_i = Aim[i];
    float ar = A_r * dt, ai = A_i * dt;
    float er = expf(ar);
    float s, c0;
    sincosf(ai, &s, &c0);
    float zr = er * c0, zi = er * s;
    float wr = zr - 1.f, wi = zi;
    float den = A_r * A_r + A_i * A_i;
    float inv = 1.f / den;
    float qr = (wr * A_r + wi * A_i) * inv;
    float qi = (wi * A_r - wr * A_i) * inv;
    float cr = Cre[i], ci = Cim[i];
    ct[i] = make_float2(2.f * (cr * qr - ci * qi), 2.f * (cr * qi + ci * qr));
    z[i] = make_float2(zr, zi);
}

// ---------------- diagonal SSM recurrence + D-skip + GELU -> bf16 hi/lo ----------------
// 2 sequences per warp (16 lanes each); 4 states/lane packed as 2x f32x2.
__global__ void k_ssm(const float* __restrict__ in, __nv_bfloat16* __restrict__ outh,
                      __nv_bfloat16* __restrict__ outl,
                      const float2* __restrict__ zarr, const float2* __restrict__ ctarr,
                      const float* __restrict__ Dv) {
    int warpId = (blockIdx.x * blockDim.x + threadIdx.x) >> 5;
    int lane = threadIdx.x & 31;
    int half = lane >> 4;
    int ll = lane & 15;
    int seq = warpId * 2 + half;          // 0 .. B*H-1
    int b = seq >> 9, h = seq & (HH - 1);

    const float2* zp = zarr + h * NN + ll * 4;
    const float2* cp = ctarr + h * NN + ll * 4;
    float2 z0 = zp[0], z1 = zp[1], z2 = zp[2], z3 = zp[3];
    float2 c0 = cp[0], c1 = cp[1], c2 = cp[2], c3 = cp[3];
    uint64_t zr01 = packf2(z0.x, z1.x), zr23 = packf2(z2.x, z3.x);
    uint64_t zi01 = packf2(z0.y, z1.y), zi23 = packf2(z2.y, z3.y);
    uint64_t nzi01 = packf2(-z0.y, -z1.y), nzi23 = packf2(-z2.y, -z3.y);
    uint64_t cr01 = packf2(c0.x, c1.x), cr23 = packf2(c2.x, c3.x);
    uint64_t nci01 = packf2(-c0.y, -c1.y), nci23 = packf2(-c2.y, -c3.y);
    float Dh = Dv[h];

    const float4* ip = (const float4*)(in + (size_t)(b * HH + h) * LL);
    __nv_bfloat16* oph = outh + (size_t)(b * HH + h) * LL;
    __nv_bfloat16* opl = outl + (size_t)(b * HH + h) * LL;

    uint64_t sr01 = packf2(0.f, 0.f), si01 = sr01, sr23 = sr01, si23 = sr01;

    float4 u4 = __ldg(ip);
    for (int l4 = 0; l4 < LL / 4; l4++) {
        float4 nx;
        if (l4 + 1 < LL / 4) nx = __ldg(ip + l4 + 1);
        float o[4];
#pragma unroll
        for (int j = 0; j < 4; j++) {
            float u = (j == 0) ? u4.x : (j == 1) ? u4.y : (j == 2) ? u4.z : u4.w;
            uint64_t uu = packf2(u, u);
            uint64_t t01 = fma2(nzi01, si01, uu);
            uint64_t t23 = fma2(nzi23, si23, uu);
            uint64_t m01 = mul2(zi01, sr01);      // uses old sr
            uint64_t m23 = mul2(zi23, sr23);
            sr01 = fma2(zr01, sr01, t01);
            sr23 = fma2(zr23, sr23, t23);
            si01 = fma2(zr01, si01, m01);
            si23 = fma2(zr23, si23, m23);
            uint64_t acc = mul2(nci23, si23);
            acc = fma2(cr23, sr23, acc);
            acc = fma2(nci01, si01, acc);
            acc = fma2(cr01, sr01, acc);
            float pl, ph;
            unpackf2(acc, pl, ph);
            float p = pl + ph;
            p += __shfl_xor_sync(0xffffffffu, p, 8);
            p += __shfl_xor_sync(0xffffffffu, p, 4);
            p += __shfl_xor_sync(0xffffffffu, p, 2);
            p += __shfl_xor_sync(0xffffffffu, p, 1);
            o[j] = fmaf(Dh, u, p);
        }
        float g0 = geluf(o[0]), g1 = geluf(o[1]);
        float g2 = geluf(o[2]), g3 = geluf(o[3]);
        uint2 hv, lv;
        split2(g0, g1, hv.x, lv.x);
        split2(g2, g3, hv.y, lv.y);
        if (ll == 0) {
            *(uint2*)(oph + l4 * 4) = hv;
            *(uint2*)(opl + l4 * 4) = lv;
        }
        u4 = nx;
    }
}

// ======================================================================
// pure-bf16 split-precision tensor-core GEMM (operands pre-split)
// ======================================================================
#define SA_STR 24
#define SB_STR 136

__device__ __forceinline__ void cp16(uint32_t dst, const void* src) {
    asm volatile("cp.async.ca.shared.global [%0], [%1], 16;\n" :: "r"(dst), "l"(src));
}
__device__ __forceinline__ void ldsm_x4(uint32_t& r0, uint32_t& r1, uint32_t& r2,
                                        uint32_t& r3, uint32_t addr) {
    asm volatile("ldmatrix.sync.aligned.m8n8.x4.shared.b16 {%0,%1,%2,%3}, [%4];"
                 : "=r"(r0), "=r"(r1), "=r"(r2), "=r"(r3) : "r"(addr));
}
__device__ __forceinline__ void ldsm_x2t(uint32_t& r0, uint32_t& r1, uint32_t addr) {
    asm volatile("ldmatrix.sync.aligned.m8n8.x2.trans.shared.b16 {%0,%1}, [%2];"
                 : "=r"(r0), "=r"(r1) : "r"(addr));
}
__device__ __forceinline__ void mma16816(float* c, const uint32_t* a, const uint32_t* b) {
    asm volatile("mma.sync.aligned.m16n8k16.row.col.f32.bf16.bf16.f32 "
                 "{%0,%1,%2,%3}, {%4,%5,%6,%7}, {%8,%9}, {%0,%1,%2,%3};"
                 : "+f"(c[0]), "+f"(c[1]), "+f"(c[2]), "+f"(c[3])
                 : "r"(a[0]), "r"(a[1]), "r"(a[2]), "r"(a[3]), "r"(b[0]), "r"(b[1]));
}

__global__ __launch_bounds__(256, 2)
void k_gemm_bf(const __nv_bfloat16* __restrict__ Ah_, const __nv_bfloat16* __restrict__ Al_,
               const __nv_bfloat16* __restrict__ Bh_, const __nv_bfloat16* __restrict__ Bl_,
               const float* __restrict__ bias, int bias_per_batch,
               float* __restrict__ Y, int O, int K,
               const float* __restrict__ xres, int final_mode) {
    __shared__ __align__(16) __nv_bfloat16 sAh[2][128][SA_STR];
    __shared__ __align__(16) __nv_bfloat16 sAl[2][128][SA_STR];
    __shared__ __align__(16) __nv_bfloat16 sBh[2][16][SB_STR];
    __shared__ __align__(16) __nv_bfloat16 sBl[2][16][SB_STR];

    int t = threadIdx.x, lane = t & 31, warp = t >> 5;
    int wo = warp >> 2, wl = warp & 3;
    int o0 = blockIdx.y * 128, l0 = blockIdx.x * 128, b = blockIdx.z;
    const __nv_bfloat16* BhB = Bh_ + (size_t)b * K * LL;
    const __nv_bfloat16* BlB = Bl_ + (size_t)b * K * LL;
    int nk = K / 16;

    int arow = t >> 1, acol = (t & 1) * 8;
    int brow = t >> 4, bcol = (t & 15) * 8;

    float acc[4][4][4];
#pragma unroll
    for (int i = 0; i < 4; i++)
#pragma unroll
        for (int j = 0; j < 4; j++)
#pragma unroll
            for (int q = 0; q < 4; q++) acc[i][j][q] = 0.f;

#define STAGE(buf, kb)                                                                     \
    do {                                                                                   \
        cp16((uint32_t)__cvta_generic_to_shared(&sAh[buf][arow][acol]),                    \
             Ah_ + (size_t)(o0 + arow) * K + (kb) + acol);                                 \
        cp16((uint32_t)__cvta_generic_to_shared(&sAl[buf][arow][acol]),                    \
             Al_ + (size_t)(o0 + arow) * K + (kb) + acol);                                 \
        cp16((uint32_t)__cvta_generic_to_shared(&sBh[buf][brow][bcol]),                    \
             BhB + (size_t)((kb) + brow) * LL + l0 + bcol);                                \
        cp16((uint32_t)__cvta_generic_to_shared(&sBl[buf][brow][bcol]),                    \
             BlB + (size_t)((kb) + brow) * LL + l0 + bcol);                                \
        asm volatile("cp.async.commit_group;\n");                                         \
    } while (0)

    STAGE(0, 0);
    asm volatile("cp.async.wait_group 0;\n");
    __syncthreads();

    int aRow = wo * 64 + (lane & 15);
    int aCol = (lane >> 4) * 8;
    uint32_t aOff = (uint32_t)((aRow * SA_STR + aCol) * 2);
    uint32_t bOff = (uint32_t)(((lane & 15) * SB_STR + wl * 32) * 2);

    for (int kc = 0; kc < nk; kc++) {
        int cur = kc & 1, nxt = cur ^ 1;
        bool more = (kc + 1) < nk;
        if (more) STAGE(nxt, (kc + 1) * 16);

        uint32_t aHb = (uint32_t)__cvta_generic_to_shared(&sAh[cur][0][0]);
        uint32_t aLb = (uint32_t)__cvta_generic_to_shared(&sAl[cur][0][0]);
        uint32_t bHb = (uint32_t)__cvta_generic_to_shared(&sBh[cur][0][0]);
        uint32_t bLb = (uint32_t)__cvta_generic_to_shared(&sBl[cur][0][0]);

        uint32_t aH[4][4], aL[4][4], bH[4][2], bL[4][2];
#pragma unroll
        for (int mi = 0; mi < 4; mi++) {
            uint32_t off = aOff + (uint32_t)(mi * 16 * SA_STR * 2);
            ldsm_x4(aH[mi][0], aH[mi][1], aH[mi][2], aH[mi][3], aHb + off);
            ldsm_x4(aL[mi][0], aL[mi][1], aL[mi][2], aL[mi][3], aLb + off);
        }
#pragma unroll
        for (int ni = 0; ni < 4; ni++) {
            uint32_t off = bOff + (uint32_t)(ni * 8 * 2);
            ldsm_x2t(bH[ni][0], bH[ni][1], bHb + off);
            ldsm_x2t(bL[ni][0], bL[ni][1], bLb + off);
        }
#pragma unroll
        for (int mi = 0; mi < 4; mi++)
#pragma unroll
            for (int ni = 0; ni < 4; ni++) {
                mma16816(acc[mi][ni], aH[mi], bH[ni]);
                mma16816(acc[mi][ni], aH[mi], bL[ni]);
                mma16816(acc[mi][ni], aL[mi], bH[ni]);
            }
        if (more) asm volatile("cp.async.wait_group 0;\n");
        __syncthreads();
    }

    // ---- epilogue ----
    int g = lane >> 2, t4 = lane & 3;
#pragma unroll
    for (int mi = 0; mi < 4; mi++) {
#pragma unroll
        for (int ni = 0; ni < 4; ni++) {
            int row0 = o0 + wo * 64 + mi * 16 + g;
            int row1 = row0 + 8;
            int col = l0 + wl * 32 + ni * 8 + t4 * 2;
            float b0 = bias_per_batch ? bias[b * O + row0] : bias[row0];
            float b1 = bias_per_batch ? bias[b * O + row1] : bias[row1];
            float v00 = acc[mi][ni][0] + b0, v01 = acc[mi][ni][1] + b0;
            float v10 = acc[mi][ni][2] + b1, v11 = acc[mi][ni][3] + b1;
            if (!final_mode) {
                float* y0 = Y + (size_t)b * O * LL + (size_t)row0 * LL + col;
                float* y1 = Y + (size_t)b * O * LL + (size_t)row1 * LL + col;
                *(float2*)y0 = make_float2(v00, v01);
                *(float2*)y1 = make_float2(v10, v11);
            } else {
                const float s = 0.70710678118654752f;
                {
                    int o = row0;
                    if (o < CC) {
                        size_t idx = (size_t)(b * CC + o) * LL + col;
                        float2 xv = *(const float2*)(xres + idx);
                        *(float2*)(Y + idx) = make_float2((xv.x + v00) * s, (xv.y + v01) * s);
                    } else {
                        size_t idx = (size_t)BB * CC * LL + (size_t)(b * CC + (o - CC)) * LL + col;
                        *(float2*)(Y + idx) = make_float2(v00, v01);
                    }
                }
                {
                    int o = row1;
                    if (o < CC) {
                        size_t idx = (size_t)(b * CC + o) * LL + col;
                        float2 xv = *(const float2*)(xres + idx);
                        *(float2*)(Y + idx) = make_float2((xv.x + v10) * s, (xv.y + v11) * s);
                    } else {
                        size_t idx = (size_t)BB * CC * LL + (size_t)(b * CC + (o - CC)) * LL + col;
                        *(float2*)(Y + idx) = make_float2(v10, v11);
                    }
                }
            }
        }
    }
#undef STAGE
}

// ---------------- fused GLU + LayerNorm ----------------
// grid (LL/16, BB), block 256. smem tile [H][16+1].
#define LT 16
__global__ void k_gluln(const float* __restrict__ t, float* __restrict__ u,
                        const float* __restrict__ g, const float* __restrict__ be) {
    __shared__ float sv[HH][LT + 1];
    __shared__ float red[2][16][LT + 1];
    __shared__ float smu[LT], srs[LT];
    int b = blockIdx.y, l0 = blockIdx.x * LT;
    const float* tb = t + (size_t)b * H2 * LL;
    // load + GLU
    for (int i = threadIdx.x; i < HH * LT; i += 256) {
        int h = i >> 4, l = i & (LT - 1);
        float a = tb[(size_t)h * LL + l0 + l];
        float gg = tb[(size_t)(h + HH) * LL + l0 + l];
        sv[h][l] = a * sigf(gg);
    }
    __syncthreads();
    // column reduce: 16 cols x 16 parts
    {
        int col = threadIdx.x & (LT - 1);
        int part = threadIdx.x >> 4;  // 0..15
        float s = 0.f, ss = 0.f;
        for (int h = part; h < HH; h += 16) {
            float v = sv[h][col];
            s += v;
            ss = fmaf(v, v, ss);
        }
        red[0][part][col] = s;
        red[1][part][col] = ss;
        __syncthreads();
        if (part == 0) {
            float S = 0.f, SS = 0.f;
#pragma unroll
            for (int p = 0; p < 16; p++) {
                S += red[0][p][col];
                SS += red[1][p][col];
            }
            float mu = S * (1.f / HH);
            float var = SS * (1.f / HH) - mu * mu;
            smu[col] = mu;
            srs[col] = rsqrtf(var + 1e-5f);
        }
        __syncthreads();
    }
    // normalize + write
    float* ub = u + (size_t)b * HH * LL;
    for (int i = threadIdx.x; i < HH * LT; i += 256) {
        int h = i >> 4, l = i & (LT - 1);
        ub[(size_t)h * LL + l0 + l] =
            (sv[h][l] - smu[l]) * srs[l] * __ldg(g + h) + __ldg(be + h);
    }
}

// ---------------- gate/filter activation -> bf16 hi/lo ----------------
__global__ void k_act(const float* __restrict__ u, __nv_bfloat16* __restrict__ zh,
                      __nv_bfloat16* __restrict__ zl) {
    int i4 = blockIdx.x * 256 + threadIdx.x;  // over B*C*L/4
    int b = i4 / (CC * LL / 4);
    int r = i4 - b * (CC * LL / 4);
    const float* ub = u + (size_t)b * HH * LL;
    float4 gt = *(const float4*)(ub + (size_t)r * 4);
    float4 fl = *(const float4*)(ub + (size_t)CC * LL + (size_t)r * 4);
    float v0 = sigf(gt.x) * tanh_fast(fl.x);
    float v1 = sigf(gt.y) * tanh_fast(fl.y);
    float v2 = sigf(gt.z) * tanh_fast(fl.z);
    float v3 = sigf(gt.w) * tanh_fast(fl.w);
    uint2 h, l;
    split2(v0, v1, h.x, l.x);
    split2(v2, v3, h.y, l.y);
    *(uint2*)(zh + (size_t)i4 * 4) = h;
    *(uint2*)(zl + (size_t)i4 * 4) = l;
}

// ---------------- launch ----------------
extern "C" void kernel_launch(void* const* d_in, const int* in_sizes, int n_in,
                              void* d_out, int out_size) {
    const float* x    = (const float*)d_in[0];
    const float* demb = (const float*)d_in[1];
    const float* dpW  = (const float*)d_in[2];
    const float* dpb  = (const float*)d_in[3];
    const float* inW  = (const float*)d_in[4];
    const float* inb  = (const float*)d_in[5];
    const float* outW = (const float*)d_in[6];
    const float* outb = (const float*)d_in[7];
    const float* ln1g = (const float*)d_in[8];
    const float* ln1b = (const float*)d_in[9];
    const float* ln2g = (const float*)d_in[10];
    const float* ln2b = (const float*)d_in[11];
    const float* s1_logdt = (const float*)d_in[12];
    const float* s1_Are   = (const float*)d_in[13];
    const float* s1_Aim   = (const float*)d_in[14];
    const float* s1_Cre   = (const float*)d_in[15];
    const float* s1_Cim   = (const float*)d_in[16];
    const float* s1_D     = (const float*)d_in[17];
    const float* s1_oW    = (const float*)d_in[18];
    const float* s1_ob    = (const float*)d_in[19];
    const float* s2_logdt = (const float*)d_in[20];
    const float* s2_Are   = (const float*)d_in[21];
    const float* s2_Aim   = (const float*)d_in[22];
    const float* s2_Cre   = (const float*)d_in[23];
    const float* s2_Cim   = (const float*)d_in[24];
    const float* s2_D     = (const float*)d_in[25];
    const float* s2_oW    = (const float*)d_in[26];
    const float* s2_ob    = (const float*)d_in[27];

    float* out = (float*)d_out;

    float *du, *dt, *de;
    float2 *dz, *dct;
    __nv_bfloat16 *bh, *bl, *wh, *wlp;
    cudaGetSymbolAddress((void**)&du, g_u);
    cudaGetSymbolAddress((void**)&dt, g_t);
    cudaGetSymbolAddress((void**)&de, g_e);
    cudaGetSymbolAddress((void**)&dz, g_z);
    cudaGetSymbolAddress((void**)&dct, g_ct);
    cudaGetSymbolAddress((void**)&bh, g_bh);
    cudaGetSymbolAddress((void**)&bl, g_bl);
    cudaGetSymbolAddress((void**)&wh, g_wh);
    cudaGetSymbolAddress((void**)&wlp, g_wl);

    const int HN = HH * NN;

    k_debias<<<BB, 256>>>(demb, dpW, dpb, inW, inb, de);
    k_wsplit<<<(HH * CC + 255) / 256, 256>>>(inW, wh + W1_OFF, wlp + W1_OFF, HH * CC);
    k_x2bf<<<BB * CC * LL / 4 / 256, 256>>>(x, bh, bl);
    // in-proj GEMM: u = in_W @ x + e(b,:)
    k_gemm_bf<<<dim3(LL / 128, HH / 128, BB), 256>>>(wh + W1_OFF, wlp + W1_OFF, bh, bl,
                                                     de, 1, du, HH, CC, nullptr, 0);
    k_prec<<<(HN + 255) / 256, 256>>>(s1_logdt, s1_Are, s1_Aim, s1_Cre, s1_Cim, dz, dct);
    k_wsplit<<<(H2 * HH + 255) / 256, 256>>>(s1_oW, wh + W2_OFF, wlp + W2_OFF, H2 * HH);
    // S4 layer 1
    k_ssm<<<(BB * HH) / 8, 128>>>(du, bh, bl, dz, dct, s1_D);
    k_gemm_bf<<<dim3(LL / 128, H2 / 128, BB), 256>>>(wh + W2_OFF, wlp + W2_OFF, bh, bl,
                                                     s1_ob, 0, dt, H2, HH, nullptr, 0);
    k_gluln<<<dim3(LL / LT, BB), 256>>>(dt, du, ln1g, ln1b);
    // S4 layer 2
    k_prec<<<(HN + 255) / 256, 256>>>(s2_logdt, s2_Are, s2_Aim, s2_Cre, s2_Cim, dz + HN, dct + HN);
    k_wsplit<<<(H2 * HH + 255) / 256, 256>>>(s2_oW, wh + W3_OFF, wlp + W3_OFF, H2 * HH);
    k_ssm<<<(BB * HH) / 8, 128>>>(du, bh, bl, dz + HN, dct + HN, s2_D);
    k_gemm_bf<<<dim3(LL / 128, H2 / 128, BB), 256>>>(wh + W3_OFF, wlp + W3_OFF, bh, bl,
                                                     s2_ob, 0, dt, H2, HH, nullptr, 0);
    k_gluln<<<dim3(LL / LT, BB), 256>>>(dt, du, ln2g, ln2b);
    // gate/filter -> bf16 pair
    k_act<<<BB * CC * LL / 4 / 256, 256>>>(du, bh, bl);
    k_wsplit<<<(HH * CC + 255) / 256, 256>>>(outW, wh + W4_OFF, wlp + W4_OFF, HH * CC);
    // out-proj fused with residual/skip split
    k_gemm_bf<<<dim3(LL / 128, HH / 128, BB), 256>>>(wh + W4_OFF, wlp + W4_OFF, bh, bl,
                                                     outb, 0, out, HH, CC, x, 1);
}